// round 1
// baseline (speedup 1.0000x reference)
#include <cuda_runtime.h>
#include <math.h>

#define BATCH 256
#define SEQT  2048
#define DIN   57
#define HID   16
#define G4    64
#define BT    (BATCH*SEQT)
#define NRED  512

// ---------------- scratch (device globals; no allocs allowed) ----------------
__device__ float g_xg[(size_t)BT * G4];    // 128 MiB: layer-0 pre-gates
__device__ float g_h2[(size_t)BT * HID];   //  32 MiB: layer-2 hidden outputs
__device__ float g_part[NRED * 32];        // per-block partial sums (s1 | s2)
__device__ float g_stats[32];              // scale[16] | shift[16]

// ---------------- activations (accurate: ~1e-7, MUFU ex2 + rcp) ----------------
__device__ __forceinline__ float sigf(float x) {
    return __fdividef(1.0f, 1.0f + __expf(-x));
}
__device__ __forceinline__ float tanhfast(float x) {
    return 1.0f - __fdividef(2.0f, 1.0f + __expf(2.0f * x));
}

// ---------------- kernel 1: xg = x @ W_ih0^T + (b_ih0 + b_hh0) ----------------
// block = 128 threads (4 warps), each warp computes 32 rows x 64 gates.
__global__ __launch_bounds__(128) void k_inproj(const float* __restrict__ x,
                                                const float* __restrict__ Wih,
                                                const float* __restrict__ bih,
                                                const float* __restrict__ bhh) {
    __shared__ float Wt[DIN * G4];     // transposed: Wt[d*64 + g]
    __shared__ float xs[128 * DIN];
    __shared__ float bsh[G4];
    const int tid = threadIdx.x;

    for (int i = tid; i < DIN * G4; i += 128) {
        int d = i >> 6, g = i & 63;
        Wt[i] = Wih[g * DIN + d];
    }
    if (tid < G4) bsh[tid] = bih[tid] + bhh[tid];
    const int row0 = blockIdx.x * 128;
    for (int i = tid; i < 128 * DIN; i += 128) xs[i] = x[(size_t)row0 * DIN + i];
    __syncthreads();

    const int lane = tid & 31, w = tid >> 5;
    const int r = w * 32 + lane;   // row within block tile

    float acc[G4];
#pragma unroll
    for (int g = 0; g < G4; ++g) acc[g] = 0.0f;

    const float4* Wt4 = (const float4*)Wt;
    for (int d = 0; d < DIN; ++d) {
        float xd = xs[r * DIN + d];               // bank-conflict free (57 ≡ 25 mod 32)
#pragma unroll
        for (int q = 0; q < 16; ++q) {
            float4 wv = Wt4[d * 16 + q];          // broadcast across warp
            acc[q * 4 + 0] += xd * wv.x;
            acc[q * 4 + 1] += xd * wv.y;
            acc[q * 4 + 2] += xd * wv.z;
            acc[q * 4 + 3] += xd * wv.w;
        }
    }

    float4* out4 = (float4*)(g_xg + (size_t)(row0 + r) * G4);
    const float4* b4 = (const float4*)bsh;
#pragma unroll
    for (int q = 0; q < 16; ++q) {
        float4 bv = b4[q];
        out4[q] = make_float4(acc[q * 4 + 0] + bv.x, acc[q * 4 + 1] + bv.y,
                              acc[q * 4 + 2] + bv.z, acc[q * 4 + 3] + bv.w);
    }
}

// ---------------- kernel 2: fused 3-layer LSTM, 1 warp per batch ----------------
// Lane l owns gates (l, l+32). Pipeline: iter `it` computes h0(it), h1(it-1), h2(it-2).
__global__ __launch_bounds__(32, 1) void k_lstm3(
    const float* __restrict__ Whh0,
    const float* __restrict__ Wih1, const float* __restrict__ Whh1,
    const float* __restrict__ bih1, const float* __restrict__ bhh1,
    const float* __restrict__ Wih2, const float* __restrict__ Whh2,
    const float* __restrict__ bih2, const float* __restrict__ bhh2) {
    const int lane = threadIdx.x;
    const int b = blockIdx.x;
    const int gA = lane, gB = lane + 32;
    const unsigned FULL = 0xffffffffu;

    float wh0A[16], wh0B[16], wh1A[16], wh1B[16], wh2A[16], wh2B[16];
    float wi1A[16], wi1B[16], wi2A[16], wi2B[16];
#pragma unroll
    for (int k = 0; k < 16; ++k) {
        wh0A[k] = Whh0[gA * 16 + k]; wh0B[k] = Whh0[gB * 16 + k];
        wh1A[k] = Whh1[gA * 16 + k]; wh1B[k] = Whh1[gB * 16 + k];
        wh2A[k] = Whh2[gA * 16 + k]; wh2B[k] = Whh2[gB * 16 + k];
        wi1A[k] = Wih1[gA * 16 + k]; wi1B[k] = Wih1[gB * 16 + k];
        wi2A[k] = Wih2[gA * 16 + k]; wi2B[k] = Wih2[gB * 16 + k];
    }
    const float b1A = bih1[gA] + bhh1[gA], b1B = bih1[gB] + bhh1[gB];
    const float b2A = bih2[gA] + bhh2[gA], b2B = bih2[gB] + bhh2[gB];

    float h0 = 0.f, c0 = 0.f, h1 = 0.f, c1 = 0.f, h2 = 0.f, c2 = 0.f;

    const float* px = g_xg + (size_t)b * SEQT * G4;
    float* ph2 = g_h2 + (size_t)b * SEQT * HID;

    // prefetch ring, distance 4
    const int PD = 4;
    float pfA[PD], pfB[PD];
#pragma unroll
    for (int u = 0; u < PD; ++u) { pfA[u] = px[u * G4 + gA]; pfB[u] = px[u * G4 + gB]; }

    const int NIT = SEQT + 4;   // 2052, multiple of 4; last 2 iters fully inactive
    for (int itb = 0; itb < NIT; itb += PD) {
#pragma unroll
        for (int u = 0; u < PD; ++u) {
            const int it = itb + u;
            float aA0 = pfA[u], aB0 = pfB[u];
            int nx = it + PD; if (nx > SEQT - 1) nx = SEQT - 1;
            pfA[u] = px[nx * G4 + gA];
            pfB[u] = px[nx * G4 + gB];

            float aA1 = b1A, aB1 = b1B, aA2 = b2A, aB2 = b2B;
#pragma unroll
            for (int k = 0; k < 16; ++k) {
                float h0k = __shfl_sync(FULL, h0, k);
                float h1k = __shfl_sync(FULL, h1, k);
                float h2k = __shfl_sync(FULL, h2, k);
                aA0 += wh0A[k] * h0k;  aB0 += wh0B[k] * h0k;
                aA1 += wi1A[k] * h0k;  aB1 += wi1B[k] * h0k;
                aA1 += wh1A[k] * h1k;  aB1 += wh1B[k] * h1k;
                aA2 += wi2A[k] * h1k;  aB2 += wi2B[k] * h1k;
                aA2 += wh2A[k] * h2k;  aB2 += wh2B[k] * h2k;
            }

            if (it < SEQT) {                         // layer 0 -> h0(it)
                float sA = sigf(aA0), tB = tanhfast(aB0), sB = sigf(aB0);
                float f = __shfl_sync(FULL, sA, (lane + 16) & 31);
                float o = __shfl_sync(FULL, sB, (lane + 16) & 31);
                c0 = f * c0 + sA * tB;
                h0 = o * tanhfast(c0);
            }
            if (it >= 1 && it <= SEQT) {             // layer 1 -> h1(it-1)
                float sA = sigf(aA1), tB = tanhfast(aB1), sB = sigf(aB1);
                float f = __shfl_sync(FULL, sA, (lane + 16) & 31);
                float o = __shfl_sync(FULL, sB, (lane + 16) & 31);
                c1 = f * c1 + sA * tB;
                h1 = o * tanhfast(c1);
            }
            if (it >= 2 && it <= SEQT + 1) {         // layer 2 -> h2(it-2), store
                float sA = sigf(aA2), tB = tanhfast(aB2), sB = sigf(aB2);
                float f = __shfl_sync(FULL, sA, (lane + 16) & 31);
                float o = __shfl_sync(FULL, sB, (lane + 16) & 31);
                c2 = f * c2 + sA * tB;
                h2 = o * tanhfast(c2);
                if (lane < 16) ph2[(it - 2) * HID + lane] = h2;
            }
        }
    }
}

// ---------------- kernel 3: masked per-channel partial sums (deterministic) ----------------
__global__ __launch_bounds__(256) void k_stats(const int* __restrict__ len) {
    __shared__ float r1[256], r2[256];
    const int tid = threadIdx.x;
    const int t0 = blockIdx.x * 256 + tid;
    const int E = BT * HID;
    float s1 = 0.f, s2 = 0.f;
    for (int e = t0; e < E; e += NRED * 256) {   // stride 131072 ≡ 0 mod 16 -> fixed channel
        int bt = e >> 4;
        int bb = bt >> 11;          // T = 2048
        int ti = bt & 2047;
        float v = (ti < len[bb]) ? g_h2[e] : 0.f;
        s1 += v; s2 += v * v;
    }
    r1[tid] = s1; r2[tid] = s2;
    __syncthreads();
    for (int s = 128; s >= 16; s >>= 1) {
        if (tid < s) { r1[tid] += r1[tid + s]; r2[tid] += r2[tid + s]; }
        __syncthreads();
    }
    if (tid < 16) {
        g_part[blockIdx.x * 32 + tid]      = r1[tid];
        g_part[blockIdx.x * 32 + 16 + tid] = r2[tid];
    }
}

// ---------------- kernel 4: final BN stats -> scale/shift ----------------
__global__ void k_finalize(const float* __restrict__ gamma, const float* __restrict__ beta) {
    const int c = threadIdx.x;
    if (c >= 16) return;
    double s1 = 0.0, s2 = 0.0;
    for (int g = 0; g < NRED; ++g) {
        s1 += (double)g_part[g * 32 + c];
        s2 += (double)g_part[g * 32 + 16 + c];
    }
    const double N = (double)BT;
    double mean = s1 / N;
    double var = s2 / N - mean * mean;
    float scale = gamma[c] * (float)(1.0 / sqrt(var + 1e-5));
    float shift = beta[c] - (float)mean * scale;
    g_stats[c] = scale;
    g_stats[16 + c] = shift;
}

// ---------------- kernel 5: mask + normalize + FC ----------------
__global__ __launch_bounds__(256) void k_fc(const int* __restrict__ len,
                                            const float* __restrict__ fcw,
                                            const float* __restrict__ fcb,
                                            float* __restrict__ out) {
    __shared__ float sw[64], sb[4], ssc[16], ssh[16];
    const int tid = threadIdx.x;
    if (tid < 64) sw[tid] = fcw[tid];
    if (tid < 4) sb[tid] = fcb[tid];
    if (tid >= 64 && tid < 80)  ssc[tid - 64] = g_stats[tid - 64];
    if (tid >= 80 && tid < 96)  ssh[tid - 80] = g_stats[16 + (tid - 80)];
    __syncthreads();

    const int bt = blockIdx.x * 256 + tid;
    const int bb = bt >> 11, ti = bt & 2047;
    const bool valid = ti < len[bb];

    const float4* h4 = (const float4*)(g_h2 + (size_t)bt * HID);
    float y[16];
#pragma unroll
    for (int q = 0; q < 4; ++q) {
        float4 v = h4[q];
        y[q * 4 + 0] = v.x; y[q * 4 + 1] = v.y; y[q * 4 + 2] = v.z; y[q * 4 + 3] = v.w;
    }
    float o0 = sb[0], o1 = sb[1], o2 = sb[2], o3 = sb[3];
#pragma unroll
    for (int c = 0; c < 16; ++c) {
        float hv = valid ? y[c] : 0.f;
        float n = hv * ssc[c] + ssh[c];
        o0 += n * sw[0 * 16 + c];
        o1 += n * sw[1 * 16 + c];
        o2 += n * sw[2 * 16 + c];
        o3 += n * sw[3 * 16 + c];
    }
    ((float4*)out)[bt] = make_float4(o0, o1, o2, o3);
}

// ---------------- launch ----------------
extern "C" void kernel_launch(void* const* d_in, const int* in_sizes, int n_in,
                              void* d_out, int out_size) {
    const float* x      = (const float*)d_in[0];
    const int*   length = (const int*)d_in[1];
    const float* Wih0 = (const float*)d_in[2],  *Whh0 = (const float*)d_in[3];
    const float* bih0 = (const float*)d_in[4],  *bhh0 = (const float*)d_in[5];
    const float* Wih1 = (const float*)d_in[6],  *Whh1 = (const float*)d_in[7];
    const float* bih1 = (const float*)d_in[8],  *bhh1 = (const float*)d_in[9];
    const float* Wih2 = (const float*)d_in[10], *Whh2 = (const float*)d_in[11];
    const float* bih2 = (const float*)d_in[12], *bhh2 = (const float*)d_in[13];
    const float* gamma = (const float*)d_in[14], *beta = (const float*)d_in[15];
    const float* fcw   = (const float*)d_in[16], *fcb  = (const float*)d_in[17];

    k_inproj<<<BT / 128, 128>>>(x, Wih0, bih0, bhh0);
    k_lstm3<<<BATCH, 32>>>(Whh0, Wih1, Whh1, bih1, bhh1, Wih2, Whh2, bih2, bhh2);
    k_stats<<<NRED, 256>>>(length);
    k_finalize<<<1, 16>>>(gamma, beta);
    k_fc<<<BT / 256, 256>>>(length, fcw, fcb, (float*)d_out);
}

// round 3
// speedup vs baseline: 1.3790x; 1.3790x over previous
#include <cuda_runtime.h>
#include <math.h>

#define BATCH 256
#define SEQT  2048
#define DIN   57
#define HID   16
#define G4    64
#define BT    (BATCH*SEQT)
#define NRED  512

typedef unsigned long long u64;

// ---------------- scratch (device globals; no allocs allowed) ----------------
__device__ float g_xg[(size_t)BT * G4];    // 128 MiB: layer-0 pre-gates
__device__ float g_h2[(size_t)BT * HID];   //  32 MiB: layer-2 hidden outputs
__device__ float g_part[NRED * 32];        // per-block partial sums (s1 | s2)
__device__ float g_stats[32];              // scale[16] | shift[16]

// ---------------- f32x2 packed helpers ----------------
__device__ __forceinline__ u64 pk2(float lo, float hi) {
    u64 r; asm("mov.b64 %0, {%1, %2};" : "=l"(r) : "f"(lo), "f"(hi)); return r;
}
__device__ __forceinline__ void unpk2(u64 v, float& lo, float& hi) {
    asm("mov.b64 {%0, %1}, %2;" : "=f"(lo), "=f"(hi) : "l"(v));
}
__device__ __forceinline__ u64 ffma2(u64 a, u64 b, u64 c) {
    u64 r; asm("fma.rn.f32x2 %0, %1, %2, %3;" : "=l"(r) : "l"(a), "l"(b), "l"(c)); return r;
}
__device__ __forceinline__ float hsum2(u64 v) {
    float lo, hi; unpk2(v, lo, hi); return lo + hi;
}

// ---------------- activations (accurate: ~1e-7) ----------------
__device__ __forceinline__ float sigf(float x) {
    return __fdividef(1.0f, 1.0f + __expf(-x));
}
__device__ __forceinline__ float tanhfast(float x) {
    return 1.0f - __fdividef(2.0f, 1.0f + __expf(2.0f * x));
}

// ---------------- kernel 1: xg = x @ W_ih0^T + (b_ih0 + b_hh0) ----------------
__global__ __launch_bounds__(128) void k_inproj(const float* __restrict__ x,
                                                const float* __restrict__ Wih,
                                                const float* __restrict__ bih,
                                                const float* __restrict__ bhh) {
    __shared__ float Wt[DIN * G4];     // transposed: Wt[d*64 + g]
    __shared__ float xs[128 * DIN];
    __shared__ float bsh[G4];
    const int tid = threadIdx.x;

    for (int i = tid; i < DIN * G4; i += 128) {
        int d = i >> 6, g = i & 63;
        Wt[i] = Wih[g * DIN + d];
    }
    if (tid < G4) bsh[tid] = bih[tid] + bhh[tid];
    const int row0 = blockIdx.x * 128;
    for (int i = tid; i < 128 * DIN; i += 128) xs[i] = x[(size_t)row0 * DIN + i];
    __syncthreads();

    const int lane = tid & 31, w = tid >> 5;
    const int r = w * 32 + lane;

    float acc[G4];
#pragma unroll
    for (int g = 0; g < G4; ++g) acc[g] = 0.0f;

    const float4* Wt4 = (const float4*)Wt;
    for (int d = 0; d < DIN; ++d) {
        float xd = xs[r * DIN + d];
#pragma unroll
        for (int q = 0; q < 16; ++q) {
            float4 wv = Wt4[d * 16 + q];
            acc[q * 4 + 0] += xd * wv.x;
            acc[q * 4 + 1] += xd * wv.y;
            acc[q * 4 + 2] += xd * wv.z;
            acc[q * 4 + 3] += xd * wv.w;
        }
    }

    float4* out4 = (float4*)(g_xg + (size_t)(row0 + r) * G4);
    const float4* b4 = (const float4*)bsh;
#pragma unroll
    for (int q = 0; q < 16; ++q) {
        float4 bv = b4[q];
        out4[q] = make_float4(acc[q * 4 + 0] + bv.x, acc[q * 4 + 1] + bv.y,
                              acc[q * 4 + 2] + bv.z, acc[q * 4 + 3] + bv.w);
    }
}

// ---------------- kernel 2: fused 3-layer LSTM, 1 warp per batch ----------------
// Lane l owns gates (l, l+32). Pipeline: iter `it` computes h0(it), h1(it-1), h2(it-2).
// Matvec uses packed f32x2 FMAs over K-pairs; weights pre-packed per k-pair.

struct LState {
    float h0, c0, h1, c1, h2, c2;
};

template<bool L0, bool L1, bool L2>
__device__ __forceinline__ void lstm_step(
    LState& s, float xA, float xB,
    const u64* wh0A, const u64* wh0B,
    const u64* wi1A, const u64* wi1B, const u64* wh1A, const u64* wh1B,
    const u64* wi2A, const u64* wi2B, const u64* wh2A, const u64* wh2B,
    float b1A, float b1B, float b2A, float b2B,
    int lane, float* st_ptr)
{
    const unsigned FULL = 0xffffffffu;
    u64 aA0 = pk2(xA, 0.f), aB0 = pk2(xB, 0.f);
    u64 aA1 = pk2(b1A, 0.f), aB1 = pk2(b1B, 0.f);
    u64 aA2 = pk2(b2A, 0.f), aB2 = pk2(b2B, 0.f);

#pragma unroll
    for (int kp = 0; kp < 8; ++kp) {
        float h0a = __shfl_sync(FULL, s.h0, 2 * kp);
        float h0b = __shfl_sync(FULL, s.h0, 2 * kp + 1);
        float h1a = __shfl_sync(FULL, s.h1, 2 * kp);
        float h1b = __shfl_sync(FULL, s.h1, 2 * kp + 1);
        float h2a = __shfl_sync(FULL, s.h2, 2 * kp);
        float h2b = __shfl_sync(FULL, s.h2, 2 * kp + 1);
        u64 h0p = pk2(h0a, h0b);
        u64 h1p = pk2(h1a, h1b);
        u64 h2p = pk2(h2a, h2b);
        aA0 = ffma2(wh0A[kp], h0p, aA0);  aB0 = ffma2(wh0B[kp], h0p, aB0);
        aA1 = ffma2(wi1A[kp], h0p, aA1);  aB1 = ffma2(wi1B[kp], h0p, aB1);
        aA1 = ffma2(wh1A[kp], h1p, aA1);  aB1 = ffma2(wh1B[kp], h1p, aB1);
        aA2 = ffma2(wi2A[kp], h1p, aA2);  aB2 = ffma2(wi2B[kp], h1p, aB2);
        aA2 = ffma2(wh2A[kp], h2p, aA2);  aB2 = ffma2(wh2B[kp], h2p, aB2);
    }

    if (L0) {
        float gA = hsum2(aA0), gB = hsum2(aB0);
        float sA = sigf(gA), sB = sigf(gB), tB = tanhfast(gB);
        float f = __shfl_xor_sync(FULL, sA, 16);
        float o = __shfl_xor_sync(FULL, sB, 16);
        s.c0 = f * s.c0 + sA * tB;
        s.h0 = o * tanhfast(s.c0);
    }
    if (L1) {
        float gA = hsum2(aA1), gB = hsum2(aB1);
        float sA = sigf(gA), sB = sigf(gB), tB = tanhfast(gB);
        float f = __shfl_xor_sync(FULL, sA, 16);
        float o = __shfl_xor_sync(FULL, sB, 16);
        s.c1 = f * s.c1 + sA * tB;
        s.h1 = o * tanhfast(s.c1);
    }
    if (L2) {
        float gA = hsum2(aA2), gB = hsum2(aB2);
        float sA = sigf(gA), sB = sigf(gB), tB = tanhfast(gB);
        float f = __shfl_xor_sync(FULL, sA, 16);
        float o = __shfl_xor_sync(FULL, sB, 16);
        s.c2 = f * s.c2 + sA * tB;
        s.h2 = o * tanhfast(s.c2);
        if (lane < 16) st_ptr[lane] = s.h2;
    }
}

__global__ __launch_bounds__(32, 1) void k_lstm3(
    const float* __restrict__ Whh0,
    const float* __restrict__ Wih1, const float* __restrict__ Whh1,
    const float* __restrict__ bih1, const float* __restrict__ bhh1,
    const float* __restrict__ Wih2, const float* __restrict__ Whh2,
    const float* __restrict__ bih2, const float* __restrict__ bhh2) {
    const int lane = threadIdx.x;
    const int b = blockIdx.x;
    const int gA = lane, gB = lane + 32;

    u64 wh0A[8], wh0B[8], wh1A[8], wh1B[8], wh2A[8], wh2B[8];
    u64 wi1A[8], wi1B[8], wi2A[8], wi2B[8];
#pragma unroll
    for (int kp = 0; kp < 8; ++kp) {
        wh0A[kp] = pk2(Whh0[gA * 16 + 2 * kp], Whh0[gA * 16 + 2 * kp + 1]);
        wh0B[kp] = pk2(Whh0[gB * 16 + 2 * kp], Whh0[gB * 16 + 2 * kp + 1]);
        wh1A[kp] = pk2(Whh1[gA * 16 + 2 * kp], Whh1[gA * 16 + 2 * kp + 1]);
        wh1B[kp] = pk2(Whh1[gB * 16 + 2 * kp], Whh1[gB * 16 + 2 * kp + 1]);
        wh2A[kp] = pk2(Whh2[gA * 16 + 2 * kp], Whh2[gA * 16 + 2 * kp + 1]);
        wh2B[kp] = pk2(Whh2[gB * 16 + 2 * kp], Whh2[gB * 16 + 2 * kp + 1]);
        wi1A[kp] = pk2(Wih1[gA * 16 + 2 * kp], Wih1[gA * 16 + 2 * kp + 1]);
        wi1B[kp] = pk2(Wih1[gB * 16 + 2 * kp], Wih1[gB * 16 + 2 * kp + 1]);
        wi2A[kp] = pk2(Wih2[gA * 16 + 2 * kp], Wih2[gA * 16 + 2 * kp + 1]);
        wi2B[kp] = pk2(Wih2[gB * 16 + 2 * kp], Wih2[gB * 16 + 2 * kp + 1]);
    }
    const float b1A = bih1[gA] + bhh1[gA], b1B = bih1[gB] + bhh1[gB];
    const float b2A = bih2[gA] + bhh2[gA], b2B = bih2[gB] + bhh2[gB];

    LState s = {0.f, 0.f, 0.f, 0.f, 0.f, 0.f};

    const float* px = g_xg + (size_t)b * SEQT * G4;
    float* ph2 = g_h2 + (size_t)b * SEQT * HID;

#define STEP(L0v, L1v, L2v, xa, xb, sp) \
    lstm_step<L0v, L1v, L2v>(s, xa, xb, wh0A, wh0B, wi1A, wi1B, wh1A, wh1B, \
                             wi2A, wi2B, wh2A, wh2B, b1A, b1B, b2A, b2B, lane, sp)

    // ---- prologue: it = 0..3 (guarded layers), init prefetch ring for 4..7
    float pfA[4], pfB[4];
    {
        float xA, xB;
        xA = px[0 * G4 + gA]; xB = px[0 * G4 + gB];
        STEP(true, false, false, xA, xB, ph2);
        xA = px[1 * G4 + gA]; xB = px[1 * G4 + gB];
        STEP(true, true, false, xA, xB, ph2);
        xA = px[2 * G4 + gA]; xB = px[2 * G4 + gB];
        STEP(true, true, true, xA, xB, ph2 + 0 * HID);
        xA = px[3 * G4 + gA]; xB = px[3 * G4 + gB];
        STEP(true, true, true, xA, xB, ph2 + 1 * HID);
#pragma unroll
        for (int u = 0; u < 4; ++u) {
            pfA[u] = px[(4 + u) * G4 + gA];
            pfB[u] = px[(4 + u) * G4 + gB];
        }
    }

    // ---- steady state: it = 4..2043, branch-free, prefetch it+4 (<= 2047)
    const float* pxa = px + gA + 8 * G4;
    const float* pxb = px + gB + 8 * G4;
    float* pst = ph2 + 2 * HID;            // store target for it=4 -> h2(2)
    for (int itb = 4; itb < 2044; itb += 4) {
#pragma unroll
        for (int u = 0; u < 4; ++u) {
            float xA = pfA[u], xB = pfB[u];
            pfA[u] = pxa[u * G4];
            pfB[u] = pxb[u * G4];
            STEP(true, true, true, xA, xB, pst);
            pst += HID;
        }
        pxa += 4 * G4;
        pxb += 4 * G4;
    }

    // ---- tail: it = 2044..2049 (ring holds 2044..2047)
    {
        STEP(true, true, true, pfA[0], pfB[0], ph2 + 2042 * HID);
        STEP(true, true, true, pfA[1], pfB[1], ph2 + 2043 * HID);
        STEP(true, true, true, pfA[2], pfB[2], ph2 + 2044 * HID);
        STEP(true, true, true, pfA[3], pfB[3], ph2 + 2045 * HID);
        STEP(false, true, true, 0.f, 0.f, ph2 + 2046 * HID);
        STEP(false, false, true, 0.f, 0.f, ph2 + 2047 * HID);
    }
#undef STEP
}

// ---------------- kernel 3: masked per-channel partial sums (deterministic) ----------------
__global__ __launch_bounds__(256) void k_stats(const int* __restrict__ len) {
    __shared__ float r1[256], r2[256];
    const int tid = threadIdx.x;
    const int t0 = blockIdx.x * 256 + tid;
    const int E = BT * HID;
    float s1 = 0.f, s2 = 0.f;
    for (int e = t0; e < E; e += NRED * 256) {   // stride ≡ 0 mod 16 -> fixed channel
        int bt = e >> 4;
        int bb = bt >> 11;
        int ti = bt & 2047;
        float v = (ti < len[bb]) ? g_h2[e] : 0.f;
        s1 += v; s2 += v * v;
    }
    r1[tid] = s1; r2[tid] = s2;
    __syncthreads();
    for (int s = 128; s >= 16; s >>= 1) {
        if (tid < s) { r1[tid] += r1[tid + s]; r2[tid] += r2[tid + s]; }
        __syncthreads();
    }
    if (tid < 16) {
        g_part[blockIdx.x * 32 + tid]      = r1[tid];
        g_part[blockIdx.x * 32 + 16 + tid] = r2[tid];
    }
}

// ---------------- kernel 4: final BN stats -> scale/shift (parallel) ----------------
__global__ __launch_bounds__(512) void k_finalize(const float* __restrict__ gamma,
                                                  const float* __restrict__ beta) {
    __shared__ double r1[512], r2[512];
    const int tid = threadIdx.x;
    const int c = tid & 15;
    const int g0 = tid >> 4;   // 0..31
    double s1 = 0.0, s2 = 0.0;
    for (int g = g0; g < NRED; g += 32) {
        s1 += (double)g_part[g * 32 + c];
        s2 += (double)g_part[g * 32 + 16 + c];
    }
    r1[tid] = s1; r2[tid] = s2;
    __syncthreads();
    for (int s = 256; s >= 16; s >>= 1) {
        if (tid < s) { r1[tid] += r1[tid + s]; r2[tid] += r2[tid + s]; }
        __syncthreads();
    }
    if (tid < 16) {
        const double N = (double)BT;
        double mean = r1[tid] / N;
        double var = r2[tid] / N - mean * mean;
        float scale = gamma[tid] * (float)(1.0 / sqrt(var + 1e-5));
        float shift = beta[tid] - (float)mean * scale;
        g_stats[tid] = scale;
        g_stats[16 + tid] = shift;
    }
}

// ---------------- kernel 5: mask + normalize + FC ----------------
__global__ __launch_bounds__(256) void k_fc(const int* __restrict__ len,
                                            const float* __restrict__ fcw,
                                            const float* __restrict__ fcb,
                                            float* __restrict__ out) {
    __shared__ float sw[64], sb[4], ssc[16], ssh[16];
    const int tid = threadIdx.x;
    if (tid < 64) sw[tid] = fcw[tid];
    if (tid < 4) sb[tid] = fcb[tid];
    if (tid >= 64 && tid < 80)  ssc[tid - 64] = g_stats[tid - 64];
    if (tid >= 80 && tid < 96)  ssh[tid - 80] = g_stats[16 + (tid - 80)];
    __syncthreads();

    const int bt = blockIdx.x * 256 + tid;
    const int bb = bt >> 11, ti = bt & 2047;
    const bool valid = ti < len[bb];

    const float4* h4 = (const float4*)(g_h2 + (size_t)bt * HID);
    float y[16];
#pragma unroll
    for (int q = 0; q < 4; ++q) {
        float4 v = h4[q];
        y[q * 4 + 0] = v.x; y[q * 4 + 1] = v.y; y[q * 4 + 2] = v.z; y[q * 4 + 3] = v.w;
    }
    float o0 = sb[0], o1 = sb[1], o2 = sb[2], o3 = sb[3];
#pragma unroll
    for (int c = 0; c < 16; ++c) {
        float hv = valid ? y[c] : 0.f;
        float n = hv * ssc[c] + ssh[c];
        o0 += n * sw[0 * 16 + c];
        o1 += n * sw[1 * 16 + c];
        o2 += n * sw[2 * 16 + c];
        o3 += n * sw[3 * 16 + c];
    }
    ((float4*)out)[bt] = make_float4(o0, o1, o2, o3);
}

// ---------------- launch ----------------
extern "C" void kernel_launch(void* const* d_in, const int* in_sizes, int n_in,
                              void* d_out, int out_size) {
    const float* x      = (const float*)d_in[0];
    const int*   length = (const int*)d_in[1];
    const float* Wih0 = (const float*)d_in[2],  *Whh0 = (const float*)d_in[3];
    const float* bih0 = (const float*)d_in[4],  *bhh0 = (const float*)d_in[5];
    const float* Wih1 = (const float*)d_in[6],  *Whh1 = (const float*)d_in[7];
    const float* bih1 = (const float*)d_in[8],  *bhh1 = (const float*)d_in[9];
    const float* Wih2 = (const float*)d_in[10], *Whh2 = (const float*)d_in[11];
    const float* bih2 = (const float*)d_in[12], *bhh2 = (const float*)d_in[13];
    const float* gamma = (const float*)d_in[14], *beta = (const float*)d_in[15];
    const float* fcw   = (const float*)d_in[16], *fcb  = (const float*)d_in[17];

    k_inproj<<<BT / 128, 128>>>(x, Wih0, bih0, bhh0);
    k_lstm3<<<BATCH, 32>>>(Whh0, Wih1, Whh1, bih1, bhh1, Wih2, Whh2, bih2, bhh2);
    k_stats<<<NRED, 256>>>(length);
    k_finalize<<<1, 512>>>(gamma, beta);
    k_fc<<<BT / 256, 256>>>(length, fcw, fcb, (float*)d_out);
}

// round 10
// speedup vs baseline: 1.3854x; 1.0046x over previous
#include <cuda_runtime.h>
#include <math.h>

#define BATCH 256
#define SEQT  2048
#define DIN   57
#define HID   16
#define G4    64
#define BT    (BATCH*SEQT)
#define NRED  512

typedef unsigned long long u64;

// ---------------- scratch (device globals; no allocs allowed) ----------------
__device__ float g_xg[(size_t)BT * G4];    // 128 MiB: layer-0 pre-gates
__device__ float g_h2[(size_t)BT * HID];   //  32 MiB: layer-2 hidden outputs
__device__ float g_part[NRED * 32];        // per-block partial sums (s1 | s2)
__device__ float g_stats[32];              // scale[16] | shift[16]

// ---------------- f32x2 packed helpers ----------------
__device__ __forceinline__ u64 pk2(float lo, float hi) {
    u64 r; asm("mov.b64 %0, {%1, %2};" : "=l"(r) : "f"(lo), "f"(hi)); return r;
}
__device__ __forceinline__ void unpk2(u64 v, float& lo, float& hi) {
    asm("mov.b64 {%0, %1}, %2;" : "=f"(lo), "=f"(hi) : "l"(v));
}
__device__ __forceinline__ u64 ffma2(u64 a, u64 b, u64 c) {
    u64 r; asm("fma.rn.f32x2 %0, %1, %2, %3;" : "=l"(r) : "l"(a), "l"(b), "l"(c)); return r;
}
__device__ __forceinline__ float hsum2(u64 v) {
    float lo, hi; unpk2(v, lo, hi); return lo + hi;
}

#define BAR() asm volatile("bar.sync 0;" ::: "memory")

// ---------------- activations (accurate: ~1e-7) ----------------
__device__ __forceinline__ float sigf(float x) {
    return __fdividef(1.0f, 1.0f + __expf(-x));
}
__device__ __forceinline__ float tanhfast(float x) {
    return 1.0f - __fdividef(2.0f, 1.0f + __expf(2.0f * x));
}

// Gate update. Lane l<16 owns gates (i_l, g_l); lane l+16 owns (f_l, o_l) and the
// (c_l, h_l) state. Only the i*g product crosses halves (1 xor-shfl).
__device__ __forceinline__ void gate_update(float gA, float gB, bool lo, float& c, float& h) {
    const unsigned FULL = 0xffffffffu;
    float sA = sigf(gA);                       // sig(i) or sig(f)
    float y  = lo ? 2.0f * gB : gB;            // tanh(g)=2*sig(2g)-1 ; sig(o)
    float s  = sigf(y);
    float vB = lo ? 2.0f * s - 1.0f : s;       // tanh(g) | sig(o)
    float ps = lo ? sA * vB : vB;              // i*g (lo) ; dummy (hi)
    float pr = __shfl_xor_sync(FULL, ps, 16);  // hi lanes receive i*g
    c = sA * c + pr;                           // hi: sig(f)*c + i*g   (lo: bounded junk)
    h = vB * tanhfast(c);                      // hi: sig(o)*tanh(c)
}

// ---------------- kernel 1: xg = x @ W_ih0^T + (b_ih0 + b_hh0) ----------------
// 128 threads = 4 quarter-groups x 32 lanes; each thread: 4 rows x 16 gates, f32x2.
#define XPAD 132
__global__ __launch_bounds__(128) void k_inproj(const float* __restrict__ x,
                                                const float* __restrict__ Wih,
                                                const float* __restrict__ bih,
                                                const float* __restrict__ bhh) {
    __shared__ __align__(16) float Wt[DIN * G4];        // Wt[d*64 + g]
    __shared__ __align__(16) float xsT[DIN * XPAD];     // xsT[d*132 + r]
    __shared__ __align__(16) float bsh[G4];
    const int tid = threadIdx.x;

    for (int i = tid; i < DIN * G4; i += 128) {
        int d = i >> 6, g = i & 63;
        Wt[i] = Wih[g * DIN + d];
    }
    if (tid < G4) bsh[tid] = bih[tid] + bhh[tid];
    const int row0 = blockIdx.x * 128;
    for (int i = tid; i < 128 * DIN; i += 128) {
        int r = i / DIN, d = i - r * DIN;
        xsT[d * XPAD + r] = x[(size_t)row0 * DIN + i];
    }
    __syncthreads();

    const int q = tid >> 5, lane = tid & 31;

    u64 acc[4][8];
#pragma unroll
    for (int r = 0; r < 4; ++r)
#pragma unroll
        for (int p = 0; p < 8; ++p) acc[r][p] = 0ull;

    for (int d = 0; d < DIN; ++d) {
        float4 xv = *(const float4*)&xsT[d * XPAD + lane * 4];
        const float4* wq = (const float4*)&Wt[d * G4 + q * 16];
        u64 w[8];
#pragma unroll
        for (int j = 0; j < 4; ++j) {
            float4 wv = wq[j];
            w[2 * j]     = pk2(wv.x, wv.y);
            w[2 * j + 1] = pk2(wv.z, wv.w);
        }
        float xr[4] = {xv.x, xv.y, xv.z, xv.w};
#pragma unroll
        for (int r = 0; r < 4; ++r) {
            u64 xs2 = pk2(xr[r], xr[r]);
#pragma unroll
            for (int p = 0; p < 8; ++p) acc[r][p] = ffma2(w[p], xs2, acc[r][p]);
        }
    }

    const float4* bq = (const float4*)&bsh[q * 16];
#pragma unroll
    for (int r = 0; r < 4; ++r) {
        int row = row0 + lane * 4 + r;
        float4* o = (float4*)(g_xg + (size_t)row * G4 + q * 16);
#pragma unroll
        for (int j = 0; j < 4; ++j) {
            float l0, h0, l1, h1;
            unpk2(acc[r][2 * j], l0, h0);
            unpk2(acc[r][2 * j + 1], l1, h1);
            float4 bb = bq[j];
            o[j] = make_float4(l0 + bb.x, h0 + bb.y, l1 + bb.z, h1 + bb.w);
        }
    }
}

// ---------------- kernel 2: 3-warp warp-specialized LSTM pipeline ----------------
// Block = 96 threads (warp w handles layer w). Step G: w0->h0(G), w1->h1(G-1), w2->h2(G-2).
// h exchanged via double-buffered smem; one bar.sync per step. Buffers pre-zeroed, so
// warm-up is correct as long as inactive warps just bar (w1 skips G=0; w2 skips G=0,1).
__global__ __launch_bounds__(96, 1) void k_lstm3(
    const float* __restrict__ Whh0,
    const float* __restrict__ Wih1, const float* __restrict__ Whh1,
    const float* __restrict__ bih1, const float* __restrict__ bhh1,
    const float* __restrict__ Wih2, const float* __restrict__ Whh2,
    const float* __restrict__ bih2, const float* __restrict__ bhh2) {
    __shared__ __align__(16) float hbuf[3][2][16];   // [layer][slot][unit]
    const int tid = threadIdx.x, lane = tid & 31, wid = tid >> 5;
    const int b = blockIdx.x;
    const bool lo = lane < 16;

    ((float*)hbuf)[tid] = 0.0f;     // 3*2*16 == 96 == blockDim
    __syncthreads();

    if (wid == 0) {
        // ---- layer 0: gates = xg(G) + Whh0 * h0(G-1)
        u64 wA[8], wB[8];
#pragma unroll
        for (int kp = 0; kp < 8; ++kp) {
            wA[kp] = pk2(Whh0[lane * 16 + 2 * kp],        Whh0[lane * 16 + 2 * kp + 1]);
            wB[kp] = pk2(Whh0[(lane + 32) * 16 + 2 * kp], Whh0[(lane + 32) * 16 + 2 * kp + 1]);
        }
        const float* px = g_xg + (size_t)b * SEQT * G4;
        float c = 0.f, h = 0.f;
        float pfA[4], pfB[4];
#pragma unroll
        for (int u = 0; u < 4; ++u) { pfA[u] = px[u * G4 + lane]; pfB[u] = px[u * G4 + 32 + lane]; }

        for (int Gb = 0; Gb < 2048; Gb += 4) {
#pragma unroll
            for (int u = 0; u < 4; ++u) {
                const int G = Gb + u;
                const u64* hp = (const u64*)hbuf[0][(G + 1) & 1];   // h0(G-1)
                u64 aA = pk2(pfA[u], 0.f), aB = pk2(pfB[u], 0.f);
                int nx = G + 4; nx = nx > SEQT - 1 ? SEQT - 1 : nx;
                pfA[u] = px[nx * G4 + lane];
                pfB[u] = px[nx * G4 + 32 + lane];
#pragma unroll
                for (int kp = 0; kp < 8; ++kp) {
                    u64 hv = hp[kp];
                    aA = ffma2(wA[kp], hv, aA);
                    aB = ffma2(wB[kp], hv, aB);
                }
                gate_update(hsum2(aA), hsum2(aB), lo, c, h);
                if (!lo) hbuf[0][G & 1][lane - 16] = h;             // h0(G)
                BAR();
            }
        }
        BAR(); BAR();                                               // G = 2048, 2049
    } else if (wid == 1) {
        // ---- layer 1: gates = b1 + Wih1 * h0(G-1) + Whh1 * h1(G-2)
        u64 wiA[8], wiB[8], whA[8], whB[8];
#pragma unroll
        for (int kp = 0; kp < 8; ++kp) {
            wiA[kp] = pk2(Wih1[lane * 16 + 2 * kp],        Wih1[lane * 16 + 2 * kp + 1]);
            wiB[kp] = pk2(Wih1[(lane + 32) * 16 + 2 * kp], Wih1[(lane + 32) * 16 + 2 * kp + 1]);
            whA[kp] = pk2(Whh1[lane * 16 + 2 * kp],        Whh1[lane * 16 + 2 * kp + 1]);
            whB[kp] = pk2(Whh1[(lane + 32) * 16 + 2 * kp], Whh1[(lane + 32) * 16 + 2 * kp + 1]);
        }
        const float bA = bih1[lane] + bhh1[lane];
        const float bB = bih1[lane + 32] + bhh1[lane + 32];
        float c = 0.f, h = 0.f;

        BAR();                                                      // G = 0 (idle)
        for (int Gb = 1; Gb < 2049; Gb += 4) {
#pragma unroll
            for (int u = 0; u < 4; ++u) {
                const int G = Gb + u;
                const u64* h0p = (const u64*)hbuf[0][(G + 1) & 1];  // h0(G-1)
                const u64* h1p = (const u64*)hbuf[1][G & 1];        // h1(G-2)
                u64 aA = pk2(bA, 0.f), aB = pk2(bB, 0.f);
                u64 dA = 0ull, dB = 0ull;
#pragma unroll
                for (int kp = 0; kp < 8; ++kp) {
                    u64 h0v = h0p[kp], h1v = h1p[kp];
                    aA = ffma2(wiA[kp], h0v, aA);
                    aB = ffma2(wiB[kp], h0v, aB);
                    dA = ffma2(whA[kp], h1v, dA);
                    dB = ffma2(whB[kp], h1v, dB);
                }
                gate_update(hsum2(aA) + hsum2(dA), hsum2(aB) + hsum2(dB), lo, c, h);
                if (!lo) hbuf[1][(G + 1) & 1][lane - 16] = h;       // h1(G-1), slot (G-1)&1
                BAR();
            }
        }
        BAR();                                                      // G = 2049 (idle)
    } else {
        // ---- layer 2: gates = b2 + Wih2 * h1(G-2) + Whh2 * h2(G-3); store h2(G-2)
        u64 wiA[8], wiB[8], whA[8], whB[8];
#pragma unroll
        for (int kp = 0; kp < 8; ++kp) {
            wiA[kp] = pk2(Wih2[lane * 16 + 2 * kp],        Wih2[lane * 16 + 2 * kp + 1]);
            wiB[kp] = pk2(Wih2[(lane + 32) * 16 + 2 * kp], Wih2[(lane + 32) * 16 + 2 * kp + 1]);
            whA[kp] = pk2(Whh2[lane * 16 + 2 * kp],        Whh2[lane * 16 + 2 * kp + 1]);
            whB[kp] = pk2(Whh2[(lane + 32) * 16 + 2 * kp], Whh2[(lane + 32) * 16 + 2 * kp + 1]);
        }
        const float bA = bih2[lane] + bhh2[lane];
        const float bB = bih2[lane + 32] + bhh2[lane + 32];
        float c = 0.f, h = 0.f;
        float* ph2 = g_h2 + (size_t)b * SEQT * HID;

        BAR(); BAR();                                               // G = 0, 1 (idle)
        for (int Gb = 2; Gb < 2050; Gb += 4) {
#pragma unroll
            for (int u = 0; u < 4; ++u) {
                const int G = Gb + u;
                const u64* h1p = (const u64*)hbuf[1][G & 1];        // h1(G-2)
                const u64* h2p = (const u64*)hbuf[2][(G + 1) & 1];  // h2(G-3)
                u64 aA = pk2(bA, 0.f), aB = pk2(bB, 0.f);
                u64 dA = 0ull, dB = 0ull;
#pragma unroll
                for (int kp = 0; kp < 8; ++kp) {
                    u64 h1v = h1p[kp], h2v = h2p[kp];
                    aA = ffma2(wiA[kp], h1v, aA);
                    aB = ffma2(wiB[kp], h1v, aB);
                    dA = ffma2(whA[kp], h2v, dA);
                    dB = ffma2(whB[kp], h2v, dB);
                }
                gate_update(hsum2(aA) + hsum2(dA), hsum2(aB) + hsum2(dB), lo, c, h);
                if (!lo) {
                    hbuf[2][G & 1][lane - 16] = h;                  // h2(G-2), slot (G-2)&1
                    ph2[(G - 2) * HID + (lane - 16)] = h;
                }
                BAR();
            }
        }
    }
}

// ---------------- kernel 3: masked per-channel partial sums (deterministic) ----------------
__global__ __launch_bounds__(256) void k_stats(const int* __restrict__ len) {
    __shared__ float r1[256], r2[256];
    const int tid = threadIdx.x;
    const int t0 = blockIdx.x * 256 + tid;
    const int E = BT * HID;
    float s1 = 0.f, s2 = 0.f;
    for (int e = t0; e < E; e += NRED * 256) {
        int bt = e >> 4;
        int bb = bt >> 11;
        int ti = bt & 2047;
        float v = (ti < len[bb]) ? g_h2[e] : 0.f;
        s1 += v; s2 += v * v;
    }
    r1[tid] = s1; r2[tid] = s2;
    __syncthreads();
    for (int s = 128; s >= 16; s >>= 1) {
        if (tid < s) { r1[tid] += r1[tid + s]; r2[tid] += r2[tid + s]; }
        __syncthreads();
    }
    if (tid < 16) {
        g_part[blockIdx.x * 32 + tid]      = r1[tid];
        g_part[blockIdx.x * 32 + 16 + tid] = r2[tid];
    }
}

// ---------------- kernel 4: final BN stats -> scale/shift (parallel) ----------------
__global__ __launch_bounds__(512) void k_finalize(const float* __restrict__ gamma,
                                                  const float* __restrict__ beta) {
    __shared__ double r1[512], r2[512];
    const int tid = threadIdx.x;
    const int c = tid & 15;
    const int g0 = tid >> 4;
    double s1 = 0.0, s2 = 0.0;
    for (int g = g0; g < NRED; g += 32) {
        s1 += (double)g_part[g * 32 + c];
        s2 += (double)g_part[g * 32 + 16 + c];
    }
    r1[tid] = s1; r2[tid] = s2;
    __syncthreads();
    for (int s = 256; s >= 16; s >>= 1) {
        if (tid < s) { r1[tid] += r1[tid + s]; r2[tid] += r2[tid + s]; }
        __syncthreads();
    }
    if (tid < 16) {
        const double N = (double)BT;
        double mean = r1[tid] / N;
        double var = r2[tid] / N - mean * mean;
        float scale = gamma[tid] * (float)(1.0 / sqrt(var + 1e-5));
        float shift = beta[tid] - (float)mean * scale;
        g_stats[tid] = scale;
        g_stats[16 + tid] = shift;
    }
}

// ---------------- kernel 5: mask + normalize + FC ----------------
__global__ __launch_bounds__(256) void k_fc(const int* __restrict__ len,
                                            const float* __restrict__ fcw,
                                            const float* __restrict__ fcb,
                                            float* __restrict__ out) {
    __shared__ float sw[64], sb[4], ssc[16], ssh[16];
    const int tid = threadIdx.x;
    if (tid < 64) sw[tid] = fcw[tid];
    if (tid < 4) sb[tid] = fcb[tid];
    if (tid >= 64 && tid < 80)  ssc[tid - 64] = g_stats[tid - 64];
    if (tid >= 80 && tid < 96)  ssh[tid - 80] = g_stats[16 + (tid - 80)];
    __syncthreads();

    const int bt = blockIdx.x * 256 + tid;
    const int bb = bt >> 11, ti = bt & 2047;
    const bool valid = ti < len[bb];

    const float4* h4 = (const float4*)(g_h2 + (size_t)bt * HID);
    float y[16];
#pragma unroll
    for (int q = 0; q < 4; ++q) {
        float4 v = h4[q];
        y[q * 4 + 0] = v.x; y[q * 4 + 1] = v.y; y[q * 4 + 2] = v.z; y[q * 4 + 3] = v.w;
    }
    float o0 = sb[0], o1 = sb[1], o2 = sb[2], o3 = sb[3];
#pragma unroll
    for (int c = 0; c < 16; ++c) {
        float hv = valid ? y[c] : 0.f;
        float n = hv * ssc[c] + ssh[c];
        o0 += n * sw[0 * 16 + c];
        o1 += n * sw[1 * 16 + c];
        o2 += n * sw[2 * 16 + c];
        o3 += n * sw[3 * 16 + c];
    }
    ((float4*)out)[bt] = make_float4(o0, o1, o2, o3);
}

// ---------------- launch ----------------
extern "C" void kernel_launch(void* const* d_in, const int* in_sizes, int n_in,
                              void* d_out, int out_size) {
    const float* x      = (const float*)d_in[0];
    const int*   length = (const int*)d_in[1];
    const float* Wih0 = (const float*)d_in[2],  *Whh0 = (const float*)d_in[3];
    const float* bih0 = (const float*)d_in[4],  *bhh0 = (const float*)d_in[5];
    const float* Wih1 = (const float*)d_in[6],  *Whh1 = (const float*)d_in[7];
    const float* bih1 = (const float*)d_in[8],  *bhh1 = (const float*)d_in[9];
    const float* Wih2 = (const float*)d_in[10], *Whh2 = (const float*)d_in[11];
    const float* bih2 = (const float*)d_in[12], *bhh2 = (const float*)d_in[13];
    const float* gamma = (const float*)d_in[14], *beta = (const float*)d_in[15];
    const float* fcw   = (const float*)d_in[16], *fcb  = (const float*)d_in[17];

    k_inproj<<<BT / 128, 128>>>(x, Wih0, bih0, bhh0);
    k_lstm3<<<BATCH, 96>>>(Whh0, Wih1, Whh1, bih1, bhh1, Wih2, Whh2, bih2, bhh2);
    k_stats<<<NRED, 256>>>(length);
    k_finalize<<<1, 512>>>(gamma, beta);
    k_fc<<<BT / 256, 256>>>(length, fcw, fcb, (float*)d_out);
}